// round 16
// baseline (speedup 1.0000x reference)
#include <cuda_runtime.h>
#include <cuda_fp16.h>
#include <cstdint>
#include <math.h>

#define BB 8
#define LL 2048
#define DD 512
#define BL (BB*LL)

// ---------------------------------------------------------------------------
// Device scratch
// ---------------------------------------------------------------------------
__device__ __align__(256) __half g_Eh[(size_t)BB*LL*LL];  // E' = exp(S)*2^-26, fp16
__device__ __align__(256) __half g_qh[BL*DD], g_ql[BL*DD];
__device__ __align__(256) __half g_kh[BL*DD], g_kl[BL*DD];
__device__ __align__(256) __half g_vh[BL*DD];
__device__ __align__(256) __half g_Wqh[DD*DD], g_Wql[DD*DD];
__device__ __align__(256) __half g_Wkh[DD*DD], g_Wkl[DD*DD];
__device__ __align__(256) __half g_Wvh[DD*DD];
__device__ __align__(256) __half g_qph[BL*DD], g_qpl[BL*DD];
__device__ __align__(256) __half g_kph[BL*DD];            // single plane
__device__ __align__(256) __half g_vpTh[BL*DD];           // [B][D][L] single plane
__device__ __align__(256) float g_crcpz[BL];
__device__ __align__(256) float g_pz[16*BL];

// pointer set for z-fused projection launches (q & k)
struct ProjArgs {
    const __half *Ah0, *Al0, *Bh0, *Bl0; const float* b0; __half *Ch0, *Cl0;
    const __half *Ah1, *Al1, *Bh1, *Bl1; const float* b1; __half *Ch1, *Cl1;
};

// ---------------------------------------------------------------------------
// Portable PTX helpers (sm_80+)
// ---------------------------------------------------------------------------
__device__ __forceinline__ uint32_t smem_u32(const void* p) {
    uint32_t a;
    asm("{ .reg .u64 t; cvta.to.shared.u64 t, %1; cvt.u32.u64 %0, t; }"
        : "=r"(a) : "l"(p));
    return a;
}

#define CP16(dst, src) \
    asm volatile("cp.async.cg.shared.global [%0], [%1], 16;" \
                 :: "r"(dst), "l"(src) : "memory")
#define CP_COMMIT() asm volatile("cp.async.commit_group;" ::: "memory")

template<int N>
__device__ __forceinline__ void cp_wait() {
    asm volatile("cp.async.wait_group %0;" :: "n"(N) : "memory");
}

#define LDSM4(r0, r1, r2, r3, addr) \
    asm volatile("ldmatrix.sync.aligned.m8n8.x4.shared.b16 {%0,%1,%2,%3}, [%4];" \
                 : "=r"(r0), "=r"(r1), "=r"(r2), "=r"(r3) : "r"(addr))

#define MMAH(d, a, b) \
    asm volatile("mma.sync.aligned.m16n8k16.row.col.f32.f16.f16.f32 " \
                 "{%0,%1,%2,%3}, {%4,%5,%6,%7}, {%8,%9}, {%0,%1,%2,%3};" \
                 : "+f"((d)[0]), "+f"((d)[1]), "+f"((d)[2]), "+f"((d)[3]) \
                 : "r"((a)[0]), "r"((a)[1]), "r"((a)[2]), "r"((a)[3]), \
                   "r"((b)[0]), "r"((b)[1]))

__device__ __forceinline__ uint32_t packh2(float a, float b) {
    __half2 t = __floats2half2_rn(a, b);
    uint32_t u; memcpy(&u, &t, 4); return u;
}
__device__ __forceinline__ void split2h(float v0, float v1,
                                        uint32_t& h, uint32_t& l) {
    float h0 = __half2float(__float2half_rn(v0));
    float h1 = __half2float(__float2half_rn(v1));
    h = packh2(v0, v1);
    l = packh2(v0 - h0, v1 - h1);
}

// Fast exp * 2^-26 on the FMA pipe (rel err ~2e-6), clamped for fp16 storage
__device__ __forceinline__ float fast_exp_s26(float x) {
    float y = x * 1.4426950408889634f;
    float t = y + 12582912.f;
    int   n = __float_as_int(t) - 0x4B400000;
    t -= 12582912.f;
    float f = y - t;
    float p = 1.3333558146e-3f;
    p = fmaf(p, f, 9.6181291076e-3f);
    p = fmaf(p, f, 5.5504108664e-2f);
    p = fmaf(p, f, 2.4022650696e-1f);
    p = fmaf(p, f, 6.9314718056e-1f);
    p = fmaf(p, f, 1.0f);
    float e = __int_as_float(__float_as_int(p) + ((n - 26) << 23));
    return fminf(e, 60000.f);
}

#define SMEM_BYTES 98304
#define SMEM1_BYTES 73728
#define SMEM2_BYTES 61440

// ---------------------------------------------------------------------------
// NT GEMM (128x128 tile), fp16 split precision, 3-term, 3-stage ring.
// ZSEL: pointer set chosen by blockIdx.z from ProjArgs (strides must be 0).
// mode 1 only: Ch (+Cl if non-null) fp16 planes row-major (+bias).
// ---------------------------------------------------------------------------
template<bool ZSEL>
__global__ void __launch_bounds__(256, 2) gemm_mma(
    const __half* __restrict__ Ah, const __half* __restrict__ Al,
    const __half* __restrict__ Bh, const __half* __restrict__ Bl,
    const float* __restrict__ bias,
    __half* __restrict__ Ch, __half* __restrict__ Cl,
    int N, int K, ProjArgs pa)
{
    constexpr int PLANE = 128 * 64;
    constexpr int STAGE = 4 * PLANE;
    constexpr int NST   = 3;
    constexpr int LOOKA = 2;
    constexpr int PAH = 0, PAL = PLANE, PBH = 2 * PLANE, PBL = 3 * PLANE;

    extern __shared__ char smem[];
    const uint32_t sbase = smem_u32(smem);
    const int tid  = threadIdx.x;
    const int lane = tid & 31;
    const int warp = tid >> 5;
    const int wm = (warp >> 1) * 32;
    const int wn = (warp & 1) * 64;
    const int m0 = blockIdx.y * 128, n0 = blockIdx.x * 128, bz = blockIdx.z;

    if (ZSEL) {
        if (bz == 1) {
            Ah = pa.Ah1; Al = pa.Al1; Bh = pa.Bh1; Bl = pa.Bl1;
            bias = pa.b1; Ch = pa.Ch1; Cl = pa.Cl1;
        } else {
            Ah = pa.Ah0; Al = pa.Al0; Bh = pa.Bh0; Bl = pa.Bl0;
            bias = pa.b0; Ch = pa.Ch0; Cl = pa.Cl0;
        }
    }

    auto swz = [](int r, int kc) -> uint32_t {
        return (uint32_t)(r * 64 + ((kc ^ ((r >> 1) & 3)) << 4));
    };

    uint32_t dOff[2]; size_t gOff[2];
    #pragma unroll
    for (int i = 0; i < 2; i++) {
        int idx = tid + i * 256;
        int r = idx >> 2, c = idx & 3;
        dOff[i] = swz(r, c);
        gOff[i] = (size_t)r * K + c * 8;
    }
    uint32_t offA[2][2], offB[2][4];
    #pragma unroll
    for (int ks = 0; ks < 2; ks++) {
        int kc = ks * 2 + (lane >> 4);
        int rbase = (lane & 7) + ((lane >> 3) & 1) * 8;
        #pragma unroll
        for (int im = 0; im < 2; im++)
            offA[ks][im] = swz(wm + im * 16 + rbase, kc);
        #pragma unroll
        for (int j4 = 0; j4 < 4; j4++)
            offB[ks][j4] = swz(wn + j4 * 16 + rbase, kc);
    }

    const __half* pAh = Ah + (size_t)m0 * K;
    const __half* pAl = Al + (size_t)m0 * K;
    const __half* pBh = Bh + (size_t)n0 * K;
    const __half* pBl = Bl + (size_t)n0 * K;

    float acc[2][8][4];
    #pragma unroll
    for (int i = 0; i < 2; i++)
        #pragma unroll
        for (int j = 0; j < 8; j++)
            #pragma unroll
            for (int c = 0; c < 4; c++) acc[i][j][c] = 0.f;

#define LOAD_STAGE(slot, kt) do { \
    uint32_t so_ = sbase + (uint32_t)(slot) * STAGE; \
    size_t ko_ = (size_t)(kt) * 32; \
    _Pragma("unroll") \
    for (int i_ = 0; i_ < 2; i_++) { \
        uint32_t d_ = so_ + dOff[i_]; \
        size_t g_ = gOff[i_] + ko_; \
        CP16(d_ + PAH, pAh + g_); \
        CP16(d_ + PBH, pBh + g_); \
        CP16(d_ + PAL, pAl + g_); \
        CP16(d_ + PBL, pBl + g_); \
    } \
} while (0)

    const int nk = K >> 5;
    LOAD_STAGE(0, 0); CP_COMMIT();
    LOAD_STAGE(1, 1); CP_COMMIT();

    int slot = 0, nslot = LOOKA;
    for (int kt = 0; kt < nk; kt++) {
        cp_wait<1>();
        __syncthreads();
        if (kt + LOOKA < nk) LOAD_STAGE(nslot, kt + LOOKA);
        CP_COMMIT();

        const uint32_t so = sbase + (uint32_t)slot * STAGE;
        #pragma unroll
        for (int ks = 0; ks < 2; ks++) {
            uint32_t a_h[2][4], a_l[2][4];
            #pragma unroll
            for (int im = 0; im < 2; im++) {
                uint32_t ad = so + offA[ks][im];
                LDSM4(a_h[im][0], a_h[im][1], a_h[im][2], a_h[im][3], ad + PAH);
                LDSM4(a_l[im][0], a_l[im][1], a_l[im][2], a_l[im][3], ad + PAL);
            }
            uint32_t b_h[8][2], b_l[8][2];
            #pragma unroll
            for (int j4 = 0; j4 < 4; j4++) {
                uint32_t bd = so + offB[ks][j4];
                LDSM4(b_h[2*j4][0], b_h[2*j4+1][0], b_h[2*j4][1], b_h[2*j4+1][1],
                      bd + PBH);
                LDSM4(b_l[2*j4][0], b_l[2*j4+1][0], b_l[2*j4][1], b_l[2*j4+1][1],
                      bd + PBL);
            }
            #pragma unroll
            for (int im = 0; im < 2; im++)
                #pragma unroll
                for (int j = 0; j < 8; j++) MMAH(acc[im][j], a_h[im], b_h[j]);
            #pragma unroll
            for (int im = 0; im < 2; im++)
                #pragma unroll
                for (int j = 0; j < 8; j++) MMAH(acc[im][j], a_h[im], b_l[j]);
            #pragma unroll
            for (int im = 0; im < 2; im++)
                #pragma unroll
                for (int j = 0; j < 8; j++) MMAH(acc[im][j], a_l[im], b_h[j]);
        }
        slot = (slot == NST - 1) ? 0 : slot + 1;
        nslot = (nslot == NST - 1) ? 0 : nslot + 1;
    }
#undef LOAD_STAGE
    __syncthreads();

    #pragma unroll
    for (int im = 0; im < 2; im++) {
        int gm = m0 + wm + im * 16 + (lane >> 2);
        #pragma unroll
        for (int j = 0; j < 8; j++) {
            int gn = n0 + wn + j * 8 + 2 * (lane & 3);
            float b0 = bias[gn], b1 = bias[gn + 1];
            uint32_t h, l;
            split2h(acc[im][j][0] + b0, acc[im][j][1] + b1, h, l);
            *reinterpret_cast<uint32_t*>(Ch + (size_t)gm * N + gn) = h;
            if (Cl) *reinterpret_cast<uint32_t*>(Cl + (size_t)gm * N + gn) = l;
            split2h(acc[im][j][2] + b0, acc[im][j][3] + b1, h, l);
            *reinterpret_cast<uint32_t*>(Ch + (size_t)(gm + 8) * N + gn) = h;
            if (Cl) *reinterpret_cast<uint32_t*>(Cl + (size_t)(gm + 8) * N + gn) = l;
        }
    }
}

// ---------------------------------------------------------------------------
// 2-term NT GEMM, 128x64 tile, 3 CTAs/SM.  KCH=32, 3 stages x 20KB.
// E' = exp(C)*2^-26 fp16 SINGLE plane (coalesced via smem) + per-tile colsums.
// ---------------------------------------------------------------------------
__global__ void __launch_bounds__(256, 3) gemm2_n64(
    const __half* __restrict__ Ah, const __half* __restrict__ Al,
    const __half* __restrict__ B,
    __half* __restrict__ Ch,
    int N, int K,
    size_t sAz, size_t sBz, size_t sCz)
{
    constexpr int PAHo  = 0;
    constexpr int PALo  = 8192;
    constexpr int PBo   = 16384;      // B: 64 rows x 64B = 4KB
    constexpr int STAGE = 20480;
    constexpr int NST   = 3;
    constexpr int LOOKA = 2;

    extern __shared__ char smem[];
    const uint32_t sbase = smem_u32(smem);
    const int tid  = threadIdx.x;
    const int lane = tid & 31;
    const int warp = tid >> 5;
    const int wm = (warp >> 1) * 32;   // 4 m-warps
    const int wn = (warp & 1) * 32;    // 2 n-warps (tile N=64)
    const int m0 = blockIdx.y * 128, n0 = blockIdx.x * 64, bz = blockIdx.z;

    auto swz = [](int r, int kc) -> uint32_t {
        return (uint32_t)(r * 64 + ((kc ^ ((r >> 1) & 3)) << 4));
    };

    // cp.async: A planes 512 chunks (2 iters), B plane 256 chunks (1 iter)
    uint32_t dOffA[2]; size_t gOffA[2];
    #pragma unroll
    for (int i = 0; i < 2; i++) {
        int idx = tid + i * 256;
        int r = idx >> 2, c = idx & 3;
        dOffA[i] = swz(r, c);
        gOffA[i] = (size_t)r * K + c * 8;
    }
    uint32_t dOffB; size_t gOffB;
    {
        int r = tid >> 2, c = tid & 3;
        dOffB = swz(r, c);
        gOffB = (size_t)r * K + c * 8;
    }

    const __half* pAh = Ah + bz * sAz + (size_t)m0 * K;
    const __half* pAl = Al + bz * sAz + (size_t)m0 * K;
    const __half* pB  = B  + bz * sBz + (size_t)n0 * K;

    float acc[2][4][4];
    #pragma unroll
    for (int i = 0; i < 2; i++)
        #pragma unroll
        for (int j = 0; j < 4; j++)
            #pragma unroll
            for (int c = 0; c < 4; c++) acc[i][j][c] = 0.f;

#define LOAD_STAGE2(slot, kt) do { \
    uint32_t so_ = sbase + (uint32_t)(slot) * STAGE; \
    size_t ko_ = (size_t)(kt) * 32; \
    _Pragma("unroll") \
    for (int i_ = 0; i_ < 2; i_++) { \
        CP16(so_ + PAHo + dOffA[i_], pAh + gOffA[i_] + ko_); \
        CP16(so_ + PALo + dOffA[i_], pAl + gOffA[i_] + ko_); \
    } \
    CP16(so_ + PBo + dOffB, pB + gOffB + ko_); \
} while (0)

    const int nk = K >> 5;
    LOAD_STAGE2(0, 0); CP_COMMIT();
    LOAD_STAGE2(1, 1); CP_COMMIT();

    int slot = 0, nslot = LOOKA;
    for (int kt = 0; kt < nk; kt++) {
        cp_wait<1>();
        __syncthreads();
        if (kt + LOOKA < nk) LOAD_STAGE2(nslot, kt + LOOKA);
        CP_COMMIT();

        const uint32_t so = sbase + (uint32_t)slot * STAGE;
        #pragma unroll
        for (int ks = 0; ks < 2; ks++) {
            const int kc = ks * 2 + (lane >> 4);
            const int rbase = (lane & 7) + ((lane >> 3) & 1) * 8;
            uint32_t a_h[2][4], a_l[2][4];
            #pragma unroll
            for (int im = 0; im < 2; im++) {
                uint32_t ad = so + swz(wm + im * 16 + rbase, kc);
                LDSM4(a_h[im][0], a_h[im][1], a_h[im][2], a_h[im][3], ad + PAHo);
                LDSM4(a_l[im][0], a_l[im][1], a_l[im][2], a_l[im][3], ad + PALo);
            }
            uint32_t b_h[4][2];
            #pragma unroll
            for (int j4 = 0; j4 < 2; j4++) {
                uint32_t bd = so + PBo + swz(wn + j4 * 16 + rbase, kc);
                LDSM4(b_h[2*j4][0], b_h[2*j4+1][0], b_h[2*j4][1], b_h[2*j4+1][1], bd);
            }
            #pragma unroll
            for (int im = 0; im < 2; im++)
                #pragma unroll
                for (int j = 0; j < 4; j++) MMAH(acc[im][j], a_h[im], b_h[j]);
            #pragma unroll
            for (int im = 0; im < 2; im++)
                #pragma unroll
                for (int j = 0; j < 4; j++) MMAH(acc[im][j], a_l[im], b_h[j]);
        }
        slot = (slot == NST - 1) ? 0 : slot + 1;
        nslot = (nslot == NST - 1) ? 0 : nslot + 1;
    }
#undef LOAD_STAGE2
    __syncthreads();

    // epilogue: exp -> smem fp16 (128 x 64, stride 72) -> coalesced out + colsums
    const int STR = 72;
    __half* sE = reinterpret_cast<__half*>(smem);
    float* sPart = reinterpret_cast<float*>(smem + 128 * STR * 2 + 64);
    __half* pCh = Ch + bz * sCz;

    float cs[4][2];
    #pragma unroll
    for (int j = 0; j < 4; j++) { cs[j][0] = 0.f; cs[j][1] = 0.f; }
    #pragma unroll
    for (int im = 0; im < 2; im++) {
        int r0 = wm + im * 16 + (lane >> 2);
        #pragma unroll
        for (int j = 0; j < 4; j++) {
            int c0 = wn + j * 8 + 2 * (lane & 3);
            float e0 = fast_exp_s26(acc[im][j][0]);
            float e1 = fast_exp_s26(acc[im][j][1]);
            float e2 = fast_exp_s26(acc[im][j][2]);
            float e3 = fast_exp_s26(acc[im][j][3]);
            *reinterpret_cast<uint32_t*>(sE + r0 * STR + c0)       = packh2(e0, e1);
            *reinterpret_cast<uint32_t*>(sE + (r0 + 8) * STR + c0) = packh2(e2, e3);
            cs[j][0] += e0 + e2;
            cs[j][1] += e1 + e3;
        }
    }
    #pragma unroll
    for (int j = 0; j < 4; j++) {
        #pragma unroll
        for (int off = 4; off <= 16; off <<= 1) {
            cs[j][0] += __shfl_xor_sync(0xffffffffu, cs[j][0], off);
            cs[j][1] += __shfl_xor_sync(0xffffffffu, cs[j][1], off);
        }
    }
    if (lane < 4) {
        int mwarp = warp >> 1;
        #pragma unroll
        for (int j = 0; j < 4; j++) {
            int col = wn + j * 8 + 2 * (lane & 3);
            sPart[mwarp * 64 + col]     = cs[j][0];
            sPart[mwarp * 64 + col + 1] = cs[j][1];
        }
    }
    __syncthreads();
    {
        int row = tid >> 1;
        int seg = (tid & 1) * 32;
        size_t gb = (size_t)(m0 + row) * N + n0 + seg;
        #pragma unroll
        for (int i = 0; i < 4; i++) {
            uint4 w = *reinterpret_cast<uint4*>(sE + row * STR + seg + i * 8);
            *reinterpret_cast<uint4*>(pCh + gb + i * 8) = w;
        }
    }
    if (tid < 64) {
        float tot = sPart[tid] + sPart[64 + tid] +
                    sPart[128 + tid] + sPart[192 + tid];
        g_pz[(size_t)blockIdx.y * BL + bz * LL + n0 + tid] = tot;
    }
}

// ---------------------------------------------------------------------------
// 1-term NT GEMM, 128x64 tile, 3 CTAs/SM.  KCH=64, 3 stages x 24KB.
// MODE 0: Cf fp32 row-major.
// MODE 2: Ch fp16 SINGLE plane transposed -> [b][n][m%LL] (+bias).
// ---------------------------------------------------------------------------
template<int MODE>
__global__ void __launch_bounds__(256, 3) gemm1_n64(
    const __half* __restrict__ A, const __half* __restrict__ B,
    const float* __restrict__ bias,
    float* __restrict__ Cf, __half* __restrict__ Ch,
    int N, int K,
    size_t sAz, size_t sBz, size_t sCz)
{
    constexpr int KCH   = 64;
    constexpr int KS    = 4;
    constexpr int PA    = 0;
    constexpr int PB    = 16384;
    constexpr int STAGE = 24576;
    constexpr int NST   = 3;
    constexpr int LOOKA = 2;

    extern __shared__ char smem[];
    const uint32_t sbase = smem_u32(smem);
    const int tid  = threadIdx.x;
    const int lane = tid & 31;
    const int warp = tid >> 5;
    const int wm = (warp >> 1) * 32;
    const int wn = (warp & 1) * 32;
    const int m0 = blockIdx.y * 128, n0 = blockIdx.x * 64, bz = blockIdx.z;

    auto swz = [](int r, int kc) -> uint32_t {
        return (uint32_t)(r * 128 + ((kc ^ (r & 7)) << 4));
    };

    uint32_t dOffA[4]; size_t gOffA[4];
    #pragma unroll
    for (int i = 0; i < 4; i++) {
        int idx = tid + i * 256;
        int r = idx >> 3, c = idx & 7;
        dOffA[i] = swz(r, c);
        gOffA[i] = (size_t)r * K + c * 8;
    }
    uint32_t dOffB[2]; size_t gOffB[2];
    #pragma unroll
    for (int i = 0; i < 2; i++) {
        int idx = tid + i * 256;
        int r = idx >> 3, c = idx & 7;
        dOffB[i] = swz(r, c);
        gOffB[i] = (size_t)r * K + c * 8;
    }

    const __half* pA = A + bz * sAz + (size_t)m0 * K;
    const __half* pB = B + bz * sBz + (size_t)n0 * K;

    float acc[2][4][4];
    #pragma unroll
    for (int i = 0; i < 2; i++)
        #pragma unroll
        for (int j = 0; j < 4; j++)
            #pragma unroll
            for (int c = 0; c < 4; c++) acc[i][j][c] = 0.f;

#define LOAD_STAGE1(slot, kt) do { \
    uint32_t so_ = sbase + (uint32_t)(slot) * STAGE; \
    size_t ko_ = (size_t)(kt) * KCH; \
    _Pragma("unroll") \
    for (int i_ = 0; i_ < 4; i_++) \
        CP16(so_ + PA + dOffA[i_], pA + gOffA[i_] + ko_); \
    _Pragma("unroll") \
    for (int i_ = 0; i_ < 2; i_++) \
        CP16(so_ + PB + dOffB[i_], pB + gOffB[i_] + ko_); \
} while (0)

    const int nk = K / KCH;
    LOAD_STAGE1(0, 0); CP_COMMIT();
    LOAD_STAGE1(1, 1); CP_COMMIT();

    int slot = 0, nslot = LOOKA;
    for (int kt = 0; kt < nk; kt++) {
        cp_wait<1>();
        __syncthreads();
        if (kt + LOOKA < nk) LOAD_STAGE1(nslot, kt + LOOKA);
        CP_COMMIT();

        const uint32_t so = sbase + (uint32_t)slot * STAGE;
        #pragma unroll
        for (int ks = 0; ks < KS; ks++) {
            const int kc = ks * 2 + (lane >> 4);
            const int rbase = (lane & 7) + ((lane >> 3) & 1) * 8;
            uint32_t a_h[2][4];
            #pragma unroll
            for (int im = 0; im < 2; im++) {
                uint32_t ad = so + PA + swz(wm + im * 16 + rbase, kc);
                LDSM4(a_h[im][0], a_h[im][1], a_h[im][2], a_h[im][3], ad);
            }
            uint32_t b_h[4][2];
            #pragma unroll
            for (int j4 = 0; j4 < 2; j4++) {
                uint32_t bd = so + PB + swz(wn + j4 * 16 + rbase, kc);
                LDSM4(b_h[2*j4][0], b_h[2*j4+1][0], b_h[2*j4][1], b_h[2*j4+1][1], bd);
            }
            #pragma unroll
            for (int im = 0; im < 2; im++)
                #pragma unroll
                for (int j = 0; j < 4; j++) MMAH(acc[im][j], a_h[im], b_h[j]);
        }
        slot = (slot == NST - 1) ? 0 : slot + 1;
        nslot = (nslot == NST - 1) ? 0 : nslot + 1;
    }
#undef LOAD_STAGE1
    __syncthreads();

    if (MODE == 0) {
        float* base = Cf + bz * sCz;
        #pragma unroll
        for (int im = 0; im < 2; im++) {
            int gm = m0 + wm + im * 16 + (lane >> 2);
            #pragma unroll
            for (int j = 0; j < 4; j++) {
                int gn = n0 + wn + j * 8 + 2 * (lane & 3);
                *reinterpret_cast<float2*>(base + (size_t)gm * N + gn) =
                    make_float2(acc[im][j][0], acc[im][j][1]);
                *reinterpret_cast<float2*>(base + (size_t)(gm + 8) * N + gn) =
                    make_float2(acc[im][j][2], acc[im][j][3]);
            }
        }
    } else {
        const int SCS = 68;
        float* sC = reinterpret_cast<float*>(smem);
        #pragma unroll
        for (int im = 0; im < 2; im++) {
            int rr = wm + im * 16 + (lane >> 2);
            #pragma unroll
            for (int j = 0; j < 4; j++) {
                int cc = wn + j * 8 + 2 * (lane & 3);
                sC[rr * SCS + cc]           = acc[im][j][0];
                sC[rr * SCS + cc + 1]       = acc[im][j][1];
                sC[(rr + 8) * SCS + cc]     = acc[im][j][2];
                sC[(rr + 8) * SCS + cc + 1] = acc[im][j][3];
            }
        }
        __syncthreads();
        const int nl = tid & 63;
        const int mh = tid >> 6;
        const float bv = bias ? bias[n0 + nl] : 0.f;
        const int b  = m0 >> 11;
        const int l0 = (m0 & (LL - 1)) + mh * 32;
        size_t base = ((size_t)b * DD + (n0 + nl)) * (size_t)LL + l0;
        for (int i = 0; i < 32; i += 8) {
            uint32_t w[4];
            #pragma unroll
            for (int p = 0; p < 4; p++) {
                float v0 = sC[(mh * 32 + i + 2 * p)     * SCS + nl] + bv;
                float v1 = sC[(mh * 32 + i + 2 * p + 1) * SCS + nl] + bv;
                w[p] = packh2(v0, v1);
            }
            *reinterpret_cast<uint4*>(Ch + base + i) =
                make_uint4(w[0], w[1], w[2], w[3]);
        }
    }
}

// ---------------------------------------------------------------------------
// fused fp32 -> fp16 hi/lo split for 3 arrays (lo plane optional per array)
// ---------------------------------------------------------------------------
__global__ void __launch_bounds__(256) cvt3(
    const float* __restrict__ s0, const float* __restrict__ s1,
    const float* __restrict__ s2,
    __half* __restrict__ h0, __half* __restrict__ l0,
    __half* __restrict__ h1, __half* __restrict__ l1,
    __half* __restrict__ h2, __half* __restrict__ l2)
{
    const float* s = (blockIdx.y == 0) ? s0 : (blockIdx.y == 1) ? s1 : s2;
    __half* h = (blockIdx.y == 0) ? h0 : (blockIdx.y == 1) ? h1 : h2;
    __half* l = (blockIdx.y == 0) ? l0 : (blockIdx.y == 1) ? l1 : l2;
    size_t i = (size_t)blockIdx.x * 256 + threadIdx.x;
    float4 v = reinterpret_cast<const float4*>(s)[i];
    uint32_t ha, la, hb, lb;
    split2h(v.x, v.y, ha, la);
    split2h(v.z, v.w, hb, lb);
    reinterpret_cast<uint32_t*>(h)[2 * i + 0] = ha;
    reinterpret_cast<uint32_t*>(h)[2 * i + 1] = hb;
    if (l) {
        reinterpret_cast<uint32_t*>(l)[2 * i + 0] = la;
        reinterpret_cast<uint32_t*>(l)[2 * i + 1] = lb;
    }
}

__global__ void __launch_bounds__(256) colsum_combine()
{
    const int c = blockIdx.x * 256 + threadIdx.x;
    float z = 0.f;
    #pragma unroll
    for (int s = 0; s < 16; s++) z += g_pz[(size_t)s * BL + c];
    g_crcpz[c] = 1.f / z;
}

// vpT[b][d][l] *= rz[b][l], single fp16 plane
__global__ void __launch_bounds__(256) scale_vpT()
{
    size_t idx = (size_t)blockIdx.x * 256 + threadIdx.x;
    size_t e0  = idx * 8;
    int l   = (int)(e0 & (LL - 1));
    int row = (int)(e0 >> 11);
    int b   = row >> 9;
    uint4 hv = reinterpret_cast<uint4*>(g_vpTh)[idx];
    const float* rz = &g_crcpz[b * LL + l];
    uint32_t hw[4] = {hv.x, hv.y, hv.z, hv.w};
    #pragma unroll
    for (int p = 0; p < 4; p++) {
        __half2 hh;
        memcpy(&hh, &hw[p], 4);
        float v0 = __half2float(hh.x) * rz[2 * p];
        float v1 = __half2float(hh.y) * rz[2 * p + 1];
        hw[p] = packh2(v0, v1);
    }
    reinterpret_cast<uint4*>(g_vpTh)[idx] = make_uint4(hw[0], hw[1], hw[2], hw[3]);
}

// ---------------------------------------------------------------------------
extern "C" void kernel_launch(void* const* d_in, const int* in_sizes, int n_in,
                              void* d_out, int out_size)
{
    const float* q  = (const float*)d_in[0];
    const float* k  = (const float*)d_in[1];
    const float* v  = (const float*)d_in[2];
    const float* Wq = (const float*)d_in[3];
    const float* bq = (const float*)d_in[4];
    const float* Wk = (const float*)d_in[5];
    const float* bk = (const float*)d_in[6];
    const float* Wv = (const float*)d_in[7];
    const float* bv = (const float*)d_in[8];
    float* out = (float*)d_out;

    __half *qh, *ql, *kh, *kl, *vh;
    __half *Wqh, *Wql, *Wkh, *Wkl, *Wvh;
    __half *qph, *qpl, *kph, *vpTh, *Eh;
    cudaGetSymbolAddress((void**)&qh, g_qh);   cudaGetSymbolAddress((void**)&ql, g_ql);
    cudaGetSymbolAddress((void**)&kh, g_kh);   cudaGetSymbolAddress((void**)&kl, g_kl);
    cudaGetSymbolAddress((void**)&vh, g_vh);
    cudaGetSymbolAddress((void**)&Wqh, g_Wqh); cudaGetSymbolAddress((void**)&Wql, g_Wql);
    cudaGetSymbolAddress((void**)&Wkh, g_Wkh); cudaGetSymbolAddress((void**)&Wkl, g_Wkl);
    cudaGetSymbolAddress((void**)&Wvh, g_Wvh);
    cudaGetSymbolAddress((void**)&qph, g_qph); cudaGetSymbolAddress((void**)&qpl, g_qpl);
    cudaGetSymbolAddress((void**)&kph, g_kph);
    cudaGetSymbolAddress((void**)&vpTh, g_vpTh);
    cudaGetSymbolAddress((void**)&Eh, g_Eh);

    cudaFuncSetAttribute((const void*)gemm_mma<true>,
                         cudaFuncAttributeMaxDynamicSharedMemorySize, SMEM_BYTES);
    cudaFuncSetAttribute((const void*)gemm2_n64,
                         cudaFuncAttributeMaxDynamicSharedMemorySize, SMEM2_BYTES);
    cudaFuncSetAttribute((const void*)gemm1_n64<0>,
                         cudaFuncAttributeMaxDynamicSharedMemorySize, SMEM1_BYTES);
    cudaFuncSetAttribute((const void*)gemm1_n64<2>,
                         cudaFuncAttributeMaxDynamicSharedMemorySize, SMEM1_BYTES);

    // 1) splits (v: hi plane only; Wv: hi plane only)
    {
        dim3 gi((BL * DD) / 1024, 3);
        cvt3<<<gi, 256>>>(q, k, v, qh, ql, kh, kl, vh, nullptr);
        dim3 gw((DD * DD) / 1024, 3);
        cvt3<<<gw, 256>>>(Wq, Wk, Wv, Wqh, Wql, Wkh, Wkl, Wvh, nullptr);
    }

    // 2a) q & k projections fused (z selects set); k writes SINGLE plane
    {
        ProjArgs pa;
        pa.Ah0 = qh; pa.Al0 = ql; pa.Bh0 = Wqh; pa.Bl0 = Wql;
        pa.b0 = bq; pa.Ch0 = qph; pa.Cl0 = qpl;
        pa.Ah1 = kh; pa.Al1 = kl; pa.Bh1 = Wkh; pa.Bl1 = Wkl;
        pa.b1 = bk; pa.Ch1 = kph; pa.Cl1 = nullptr;
        dim3 gqk(DD / 128, BL / 128, 2);
        gemm_mma<true><<<gqk, 256, SMEM_BYTES>>>(
            nullptr, nullptr, nullptr, nullptr, nullptr,
            nullptr, nullptr, DD, DD, pa);
    }

    // 2b) v projection: 1-term, 128x64 tile, 3 CTAs/SM
    {
        dim3 gv(DD / 64, BL / 128, 1);
        gemm1_n64<2><<<gv, 256, SMEM1_BYTES>>>(
            vh, Wvh, bv, nullptr, vpTh, DD, DD, 0, 0, 0);
    }

    // 3) E'[b] = exp(qp kp^T)*2^-26: 2-term, 128x64 tile, 3 CTAs/SM + colsums
    {
        dim3 gs(LL / 64, LL / 128, BB);
        gemm2_n64<<<gs, 256, SMEM2_BYTES>>>(
            qph, qpl, kph, Eh,
            LL, DD,
            (size_t)LL * DD, (size_t)LL * DD, (size_t)LL * LL);
    }

    // 4) rz = 1/colsum(E'); fold into vpT
    colsum_combine<<<BL / 256, 256>>>();
    scale_vpT<<<(BL * DD) / (8 * 256), 256>>>();

    // 5) out[b] = E'[b] @ vpT'[b]^T  (1-term, 128x64 tile, 3 CTAs/SM)
    {
        dim3 go(DD / 64, LL / 128, BB);
        gemm1_n64<0><<<go, 256, SMEM1_BYTES>>>(
            Eh, vpTh, nullptr, out, nullptr,
            DD, LL,
            (size_t)LL * LL, (size_t)DD * LL,
            (size_t)LL * DD);
    }
}

// round 17
// speedup vs baseline: 1.0070x; 1.0070x over previous
#include <cuda_runtime.h>
#include <cuda_fp16.h>
#include <cstdint>
#include <math.h>

#define BB 8
#define LL 2048
#define DD 512
#define BL (BB*LL)

// ---------------------------------------------------------------------------
// Device scratch
// ---------------------------------------------------------------------------
__device__ __align__(256) __half g_Eh[(size_t)BB*LL*LL];  // E' = exp(S)*2^-26, fp16
__device__ __align__(256) __half g_qh[BL*DD], g_ql[BL*DD];
__device__ __align__(256) __half g_kh[BL*DD], g_kl[BL*DD];
__device__ __align__(256) __half g_vh[BL*DD];
__device__ __align__(256) __half g_Wqh[DD*DD], g_Wql[DD*DD];
__device__ __align__(256) __half g_Wkh[DD*DD], g_Wkl[DD*DD];
__device__ __align__(256) __half g_Wvh[DD*DD];
__device__ __align__(256) __half g_qph[BL*DD], g_qpl[BL*DD];
__device__ __align__(256) __half g_kph[BL*DD];            // single plane
__device__ __align__(256) __half g_vpTh[BL*DD];           // [B][D][L] single plane
__device__ __align__(256) float g_crcpz[BL];
__device__ __align__(256) float g_pz[16*BL];

// pointer set for z-fused projection launches (q & k)
struct ProjArgs {
    const __half *Ah0, *Al0, *Bh0, *Bl0; const float* b0; __half *Ch0, *Cl0;
    const __half *Ah1, *Al1, *Bh1, *Bl1; const float* b1; __half *Ch1, *Cl1;
};

// ---------------------------------------------------------------------------
// Portable PTX helpers (sm_80+)
// ---------------------------------------------------------------------------
__device__ __forceinline__ uint32_t smem_u32(const void* p) {
    uint32_t a;
    asm("{ .reg .u64 t; cvta.to.shared.u64 t, %1; cvt.u32.u64 %0, t; }"
        : "=r"(a) : "l"(p));
    return a;
}

#define CP16(dst, src) \
    asm volatile("cp.async.cg.shared.global [%0], [%1], 16;" \
                 :: "r"(dst), "l"(src) : "memory")
#define CP_COMMIT() asm volatile("cp.async.commit_group;" ::: "memory")

template<int N>
__device__ __forceinline__ void cp_wait() {
    asm volatile("cp.async.wait_group %0;" :: "n"(N) : "memory");
}

#define LDSM4(r0, r1, r2, r3, addr) \
    asm volatile("ldmatrix.sync.aligned.m8n8.x4.shared.b16 {%0,%1,%2,%3}, [%4];" \
                 : "=r"(r0), "=r"(r1), "=r"(r2), "=r"(r3) : "r"(addr))

#define MMAH(d, a, b) \
    asm volatile("mma.sync.aligned.m16n8k16.row.col.f32.f16.f16.f32 " \
                 "{%0,%1,%2,%3}, {%4,%5,%6,%7}, {%8,%9}, {%0,%1,%2,%3};" \
                 : "+f"((d)[0]), "+f"((d)[1]), "+f"((d)[2]), "+f"((d)[3]) \
                 : "r"((a)[0]), "r"((a)[1]), "r"((a)[2]), "r"((a)[3]), \
                   "r"((b)[0]), "r"((b)[1]))

__device__ __forceinline__ uint32_t packh2(float a, float b) {
    __half2 t = __floats2half2_rn(a, b);
    uint32_t u; memcpy(&u, &t, 4); return u;
}
__device__ __forceinline__ void split2h(float v0, float v1,
                                        uint32_t& h, uint32_t& l) {
    float h0 = __half2float(__float2half_rn(v0));
    float h1 = __half2float(__float2half_rn(v1));
    h = packh2(v0, v1);
    l = packh2(v0 - h0, v1 - h1);
}

// Fast exp * 2^-26 on the FMA pipe (rel err ~2e-6), clamped for fp16 storage
__device__ __forceinline__ float fast_exp_s26(float x) {
    float y = x * 1.4426950408889634f;
    float t = y + 12582912.f;
    int   n = __float_as_int(t) - 0x4B400000;
    t -= 12582912.f;
    float f = y - t;
    float p = 1.3333558146e-3f;
    p = fmaf(p, f, 9.6181291076e-3f);
    p = fmaf(p, f, 5.5504108664e-2f);
    p = fmaf(p, f, 2.4022650696e-1f);
    p = fmaf(p, f, 6.9314718056e-1f);
    p = fmaf(p, f, 1.0f);
    float e = __int_as_float(__float_as_int(p) + ((n - 26) << 23));
    return fminf(e, 60000.f);
}

#define SMEM_BYTES 98304
#define SMEM1_BYTES 73728

// ---------------------------------------------------------------------------
// NT GEMM (128x128 tile), fp16 split precision, mma.sync, multi-stage ring.
// TERMS=3: Ah*Bh + Ah*Bl + Al*Bh, KCH=32, 4 planes x 8KB  -> 3 stages.
// TERMS=2: Ah*Bh + Al*Bh,         KCH=32, 3 planes x 8KB  -> 4 stages.
// ZSEL: pointer set chosen by blockIdx.z from ProjArgs (strides must be 0).
// mode 1: Ch (+Cl if non-null) fp16 planes row-major (+bias).
// mode 3: Ch = exp(C)*2^-26 fp16 SINGLE plane (coalesced via smem) + colsums.
// ---------------------------------------------------------------------------
template<int TERMS, bool ZSEL>
__global__ void __launch_bounds__(256, 2) gemm_mma(
    const __half* __restrict__ Ah, const __half* __restrict__ Al,
    const __half* __restrict__ Bh, const __half* __restrict__ Bl,
    const float* __restrict__ bias,
    __half* __restrict__ Ch, __half* __restrict__ Cl,
    int N, int K,
    size_t sAz, size_t sBz, size_t sCz,
    int mode, ProjArgs pa)
{
    constexpr bool HAS_BL = (TERMS == 3);
    constexpr int PLANE = 128 * 64;
    constexpr int NPL   = HAS_BL ? 4 : 3;
    constexpr int STAGE = NPL * PLANE;
    constexpr int NST   = SMEM_BYTES / STAGE;     // 3 or 4
    constexpr int LOOKA = NST - 1;
    constexpr int PAH = 0, PAL = PLANE, PBH = 2 * PLANE;
    constexpr int PBL = HAS_BL ? 3 * PLANE : 0;

    extern __shared__ char smem[];
    const uint32_t sbase = smem_u32(smem);
    const int tid  = threadIdx.x;
    const int lane = tid & 31;
    const int warp = tid >> 5;
    const int wm = (warp >> 1) * 32;
    const int wn = (warp & 1) * 64;
    const int m0 = blockIdx.y * 128, n0 = blockIdx.x * 128, bz = blockIdx.z;

    if (ZSEL) {
        if (bz == 1) {
            Ah = pa.Ah1; Al = pa.Al1; Bh = pa.Bh1; Bl = pa.Bl1;
            bias = pa.b1; Ch = pa.Ch1; Cl = pa.Cl1;
        } else {
            Ah = pa.Ah0; Al = pa.Al0; Bh = pa.Bh0; Bl = pa.Bl0;
            bias = pa.b0; Ch = pa.Ch0; Cl = pa.Cl0;
        }
    }

    auto swz = [](int r, int kc) -> uint32_t {
        return (uint32_t)(r * 64 + ((kc ^ ((r >> 1) & 3)) << 4));
    };

    uint32_t dOff[2]; size_t gOff[2];
    #pragma unroll
    for (int i = 0; i < 2; i++) {
        int idx = tid + i * 256;
        int r = idx >> 2, c = idx & 3;
        dOff[i] = swz(r, c);
        gOff[i] = (size_t)r * K + c * 8;
    }
    uint32_t offA[2][2], offB[2][4];
    #pragma unroll
    for (int ks = 0; ks < 2; ks++) {
        int kc = ks * 2 + (lane >> 4);
        int rbase = (lane & 7) + ((lane >> 3) & 1) * 8;
        #pragma unroll
        for (int im = 0; im < 2; im++)
            offA[ks][im] = swz(wm + im * 16 + rbase, kc);
        #pragma unroll
        for (int j4 = 0; j4 < 4; j4++)
            offB[ks][j4] = swz(wn + j4 * 16 + rbase, kc);
    }

    const __half* pAh = Ah + bz * sAz + (size_t)m0 * K;
    const __half* pAl = Al + bz * sAz + (size_t)m0 * K;
    const __half* pBh = Bh + bz * sBz + (size_t)n0 * K;
    const __half* pBl = HAS_BL ? Bl + bz * sBz + (size_t)n0 * K : nullptr;

    float acc[2][8][4];
    #pragma unroll
    for (int i = 0; i < 2; i++)
        #pragma unroll
        for (int j = 0; j < 8; j++)
            #pragma unroll
            for (int c = 0; c < 4; c++) acc[i][j][c] = 0.f;

#define LOAD_STAGE(slot, kt) do { \
    uint32_t so_ = sbase + (uint32_t)(slot) * STAGE; \
    size_t ko_ = (size_t)(kt) * 32; \
    _Pragma("unroll") \
    for (int i_ = 0; i_ < 2; i_++) { \
        uint32_t d_ = so_ + dOff[i_]; \
        size_t g_ = gOff[i_] + ko_; \
        CP16(d_ + PAH, pAh + g_); \
        CP16(d_ + PBH, pBh + g_); \
        CP16(d_ + PAL, pAl + g_); \
        if (HAS_BL) CP16(d_ + PBL, pBl + g_); \
    } \
} while (0)

    const int nk = K >> 5;
    #pragma unroll
    for (int p = 0; p < LOOKA; p++) {
        if (p < nk) LOAD_STAGE(p, p);
        CP_COMMIT();
    }

    int slot = 0, nslot = LOOKA;
    for (int kt = 0; kt < nk; kt++) {
        cp_wait<LOOKA - 1>();
        __syncthreads();
        if (kt + LOOKA < nk) LOAD_STAGE(nslot, kt + LOOKA);
        CP_COMMIT();

        const uint32_t so = sbase + (uint32_t)slot * STAGE;
        #pragma unroll
        for (int ks = 0; ks < 2; ks++) {
            uint32_t a_h[2][4], a_l[2][4];
            #pragma unroll
            for (int im = 0; im < 2; im++) {
                uint32_t ad = so + offA[ks][im];
                LDSM4(a_h[im][0], a_h[im][1], a_h[im][2], a_h[im][3], ad + PAH);
                LDSM4(a_l[im][0], a_l[im][1], a_l[im][2], a_l[im][3], ad + PAL);
            }
            uint32_t b_h[8][2], b_l[8][2];
            #pragma unroll
            for (int j4 = 0; j4 < 4; j4++) {
                uint32_t bd = so + offB[ks][j4];
                LDSM4(b_h[2*j4][0], b_h[2*j4+1][0], b_h[2*j4][1], b_h[2*j4+1][1],
                      bd + PBH);
                if (HAS_BL)
                    LDSM4(b_l[2*j4][0], b_l[2*j4+1][0], b_l[2*j4][1], b_l[2*j4+1][1],
                          bd + PBL);
            }
            #pragma unroll
            for (int im = 0; im < 2; im++)
                #pragma unroll
                for (int j = 0; j < 8; j++) MMAH(acc[im][j], a_h[im], b_h[j]);
            if (HAS_BL) {
                #pragma unroll
                for (int im = 0; im < 2; im++)
                    #pragma unroll
                    for (int j = 0; j < 8; j++) MMAH(acc[im][j], a_h[im], b_l[j]);
            }
            #pragma unroll
            for (int im = 0; im < 2; im++)
                #pragma unroll
                for (int j = 0; j < 8; j++) MMAH(acc[im][j], a_l[im], b_h[j]);
        }
        slot = (slot == NST - 1) ? 0 : slot + 1;
        nslot = (nslot == NST - 1) ? 0 : nslot + 1;
    }
#undef LOAD_STAGE
    __syncthreads();

    __half* pCh = Ch + bz * sCz;
    __half* pCl = Cl ? Cl + bz * sCz : nullptr;

    if (mode == 1) {
        #pragma unroll
        for (int im = 0; im < 2; im++) {
            int gm = m0 + wm + im * 16 + (lane >> 2);
            #pragma unroll
            for (int j = 0; j < 8; j++) {
                int gn = n0 + wn + j * 8 + 2 * (lane & 3);
                float b0 = bias[gn], b1 = bias[gn + 1];
                uint32_t h, l;
                split2h(acc[im][j][0] + b0, acc[im][j][1] + b1, h, l);
                *reinterpret_cast<uint32_t*>(pCh + (size_t)gm * N + gn) = h;
                if (pCl) *reinterpret_cast<uint32_t*>(pCl + (size_t)gm * N + gn) = l;
                split2h(acc[im][j][2] + b0, acc[im][j][3] + b1, h, l);
                *reinterpret_cast<uint32_t*>(pCh + (size_t)(gm + 8) * N + gn) = h;
                if (pCl) *reinterpret_cast<uint32_t*>(pCl + (size_t)(gm + 8) * N + gn) = l;
            }
        }
    } else {
        // mode 3: E' = exp(S)*2^-26 fp16 single plane via smem; fp32 colsums
        const int STR = 136;
        __half* sE = reinterpret_cast<__half*>(smem);
        float* sPart = reinterpret_cast<float*>(smem + 128 * STR * 2 + 64);
        float cs[8][2];
        #pragma unroll
        for (int j = 0; j < 8; j++) { cs[j][0] = 0.f; cs[j][1] = 0.f; }
        #pragma unroll
        for (int im = 0; im < 2; im++) {
            int r0 = wm + im * 16 + (lane >> 2);
            #pragma unroll
            for (int j = 0; j < 8; j++) {
                int c0 = wn + j * 8 + 2 * (lane & 3);
                float e0 = fast_exp_s26(acc[im][j][0]);
                float e1 = fast_exp_s26(acc[im][j][1]);
                float e2 = fast_exp_s26(acc[im][j][2]);
                float e3 = fast_exp_s26(acc[im][j][3]);
                *reinterpret_cast<uint32_t*>(sE + r0 * STR + c0)       = packh2(e0, e1);
                *reinterpret_cast<uint32_t*>(sE + (r0 + 8) * STR + c0) = packh2(e2, e3);
                cs[j][0] += e0 + e2;
                cs[j][1] += e1 + e3;
            }
        }
        #pragma unroll
        for (int j = 0; j < 8; j++) {
            #pragma unroll
            for (int off = 4; off <= 16; off <<= 1) {
                cs[j][0] += __shfl_xor_sync(0xffffffffu, cs[j][0], off);
                cs[j][1] += __shfl_xor_sync(0xffffffffu, cs[j][1], off);
            }
        }
        __syncthreads();
        {
            int row = tid >> 1;
            int seg = (tid & 1) * 64;
            size_t gb = (size_t)(m0 + row) * N + n0 + seg;
            #pragma unroll
            for (int i = 0; i < 8; i++) {
                uint4 w = *reinterpret_cast<uint4*>(sE + row * STR + seg + i * 8);
                *reinterpret_cast<uint4*>(pCh + gb + i * 8) = w;
            }
        }
        if (lane < 4) {
            int mwarp = warp >> 1;
            #pragma unroll
            for (int j = 0; j < 8; j++) {
                int col = wn + j * 8 + 2 * (lane & 3);
                sPart[mwarp * 128 + col]     = cs[j][0];
                sPart[mwarp * 128 + col + 1] = cs[j][1];
            }
        }
        __syncthreads();
        if (tid < 128) {
            float tot = sPart[tid] + sPart[128 + tid] +
                        sPart[256 + tid] + sPart[384 + tid];
            g_pz[(size_t)blockIdx.y * BL + bz * LL + n0 + tid] = tot;
        }
    }
}

// ---------------------------------------------------------------------------
// 1-term NT GEMM, 128x64 tile, 3 CTAs/SM.  KCH=64, 3 stages x 24KB.
// MODE 0: Cf fp32 row-major.
// MODE 2: Ch fp16 SINGLE plane transposed -> [b][n][m%LL] (+bias).
// ---------------------------------------------------------------------------
template<int MODE>
__global__ void __launch_bounds__(256, 3) gemm1_n64(
    const __half* __restrict__ A, const __half* __restrict__ B,
    const float* __restrict__ bias,
    float* __restrict__ Cf, __half* __restrict__ Ch,
    int N, int K,
    size_t sAz, size_t sBz, size_t sCz)
{
    constexpr int KCH   = 64;
    constexpr int KS    = 4;
    constexpr int PA    = 0;
    constexpr int PB    = 16384;
    constexpr int STAGE = 24576;
    constexpr int NST   = 3;
    constexpr int LOOKA = 2;

    extern __shared__ char smem[];
    const uint32_t sbase = smem_u32(smem);
    const int tid  = threadIdx.x;
    const int lane = tid & 31;
    const int warp = tid >> 5;
    const int wm = (warp >> 1) * 32;
    const int wn = (warp & 1) * 32;
    const int m0 = blockIdx.y * 128, n0 = blockIdx.x * 64, bz = blockIdx.z;

    auto swz = [](int r, int kc) -> uint32_t {
        return (uint32_t)(r * 128 + ((kc ^ (r & 7)) << 4));
    };

    uint32_t dOffA[4]; size_t gOffA[4];
    #pragma unroll
    for (int i = 0; i < 4; i++) {
        int idx = tid + i * 256;
        int r = idx >> 3, c = idx & 7;
        dOffA[i] = swz(r, c);
        gOffA[i] = (size_t)r * K + c * 8;
    }
    uint32_t dOffB[2]; size_t gOffB[2];
    #pragma unroll
    for (int i = 0; i < 2; i++) {
        int idx = tid + i * 256;
        int r = idx >> 3, c = idx & 7;
        dOffB[i] = swz(r, c);
        gOffB[i] = (size_t)r * K + c * 8;
    }

    const __half* pA = A + bz * sAz + (size_t)m0 * K;
    const __half* pB = B + bz * sBz + (size_t)n0 * K;

    float acc[2][4][4];
    #pragma unroll
    for (int i = 0; i < 2; i++)
        #pragma unroll
        for (int j = 0; j < 4; j++)
            #pragma unroll
            for (int c = 0; c < 4; c++) acc[i][j][c] = 0.f;

#define LOAD_STAGE1(slot, kt) do { \
    uint32_t so_ = sbase + (uint32_t)(slot) * STAGE; \
    size_t ko_ = (size_t)(kt) * KCH; \
    _Pragma("unroll") \
    for (int i_ = 0; i_ < 4; i_++) \
        CP16(so_ + PA + dOffA[i_], pA + gOffA[i_] + ko_); \
    _Pragma("unroll") \
    for (int i_ = 0; i_ < 2; i_++) \
        CP16(so_ + PB + dOffB[i_], pB + gOffB[i_] + ko_); \
} while (0)

    const int nk = K / KCH;
    LOAD_STAGE1(0, 0); CP_COMMIT();
    LOAD_STAGE1(1, 1); CP_COMMIT();

    int slot = 0, nslot = LOOKA;
    for (int kt = 0; kt < nk; kt++) {
        cp_wait<1>();
        __syncthreads();
        if (kt + LOOKA < nk) LOAD_STAGE1(nslot, kt + LOOKA);
        CP_COMMIT();

        const uint32_t so = sbase + (uint32_t)slot * STAGE;
        #pragma unroll
        for (int ks = 0; ks < KS; ks++) {
            const int kc = ks * 2 + (lane >> 4);
            const int rbase = (lane & 7) + ((lane >> 3) & 1) * 8;
            uint32_t a_h[2][4];
            #pragma unroll
            for (int im = 0; im < 2; im++) {
                uint32_t ad = so + PA + swz(wm + im * 16 + rbase, kc);
                LDSM4(a_h[im][0], a_h[im][1], a_h[im][2], a_h[im][3], ad);
            }
            uint32_t b_h[4][2];
            #pragma unroll
            for (int j4 = 0; j4 < 2; j4++) {
                uint32_t bd = so + PB + swz(wn + j4 * 16 + rbase, kc);
                LDSM4(b_h[2*j4][0], b_h[2*j4+1][0], b_h[2*j4][1], b_h[2*j4+1][1], bd);
            }
            #pragma unroll
            for (int im = 0; im < 2; im++)
                #pragma unroll
                for (int j = 0; j < 4; j++) MMAH(acc[im][j], a_h[im], b_h[j]);
        }
        slot = (slot == NST - 1) ? 0 : slot + 1;
        nslot = (nslot == NST - 1) ? 0 : nslot + 1;
    }
#undef LOAD_STAGE1
    __syncthreads();

    if (MODE == 0) {
        float* base = Cf + bz * sCz;
        #pragma unroll
        for (int im = 0; im < 2; im++) {
            int gm = m0 + wm + im * 16 + (lane >> 2);
            #pragma unroll
            for (int j = 0; j < 4; j++) {
                int gn = n0 + wn + j * 8 + 2 * (lane & 3);
                *reinterpret_cast<float2*>(base + (size_t)gm * N + gn) =
                    make_float2(acc[im][j][0], acc[im][j][1]);
                *reinterpret_cast<float2*>(base + (size_t)(gm + 8) * N + gn) =
                    make_float2(acc[im][j][2], acc[im][j][3]);
            }
        }
    } else {
        const int SCS = 68;
        float* sC = reinterpret_cast<float*>(smem);
        #pragma unroll
        for (int im = 0; im < 2; im++) {
            int rr = wm + im * 16 + (lane >> 2);
            #pragma unroll
            for (int j = 0; j < 4; j++) {
                int cc = wn + j * 8 + 2 * (lane & 3);
                sC[rr * SCS + cc]           = acc[im][j][0];
                sC[rr * SCS + cc + 1]       = acc[im][j][1];
                sC[(rr + 8) * SCS + cc]     = acc[im][j][2];
                sC[(rr + 8) * SCS + cc + 1] = acc[im][j][3];
            }
        }
        __syncthreads();
        const int nl = tid & 63;
        const int mh = tid >> 6;
        const float bv = bias ? bias[n0 + nl] : 0.f;
        const int b  = m0 >> 11;
        const int l0 = (m0 & (LL - 1)) + mh * 32;
        size_t base = ((size_t)b * DD + (n0 + nl)) * (size_t)LL + l0;
        for (int i = 0; i < 32; i += 8) {
            uint32_t w[4];
            #pragma unroll
            for (int p = 0; p < 4; p++) {
                float v0 = sC[(mh * 32 + i + 2 * p)     * SCS + nl] + bv;
                float v1 = sC[(mh * 32 + i + 2 * p + 1) * SCS + nl] + bv;
                w[p] = packh2(v0, v1);
            }
            *reinterpret_cast<uint4*>(Ch + base + i) =
                make_uint4(w[0], w[1], w[2], w[3]);
        }
    }
}

// ---------------------------------------------------------------------------
// fused fp32 -> fp16 hi/lo split for 3 arrays (lo plane optional per array)
// ---------------------------------------------------------------------------
__global__ void __launch_bounds__(256) cvt3(
    const float* __restrict__ s0, const float* __restrict__ s1,
    const float* __restrict__ s2,
    __half* __restrict__ h0, __half* __restrict__ l0,
    __half* __restrict__ h1, __half* __restrict__ l1,
    __half* __restrict__ h2, __half* __restrict__ l2)
{
    const float* s = (blockIdx.y == 0) ? s0 : (blockIdx.y == 1) ? s1 : s2;
    __half* h = (blockIdx.y == 0) ? h0 : (blockIdx.y == 1) ? h1 : h2;
    __half* l = (blockIdx.y == 0) ? l0 : (blockIdx.y == 1) ? l1 : l2;
    size_t i = (size_t)blockIdx.x * 256 + threadIdx.x;
    float4 v = reinterpret_cast<const float4*>(s)[i];
    uint32_t ha, la, hb, lb;
    split2h(v.x, v.y, ha, la);
    split2h(v.z, v.w, hb, lb);
    reinterpret_cast<uint32_t*>(h)[2 * i + 0] = ha;
    reinterpret_cast<uint32_t*>(h)[2 * i + 1] = hb;
    if (l) {
        reinterpret_cast<uint32_t*>(l)[2 * i + 0] = la;
        reinterpret_cast<uint32_t*>(l)[2 * i + 1] = lb;
    }
}

__global__ void __launch_bounds__(256) colsum_combine()
{
    const int c = blockIdx.x * 256 + threadIdx.x;
    float z = 0.f;
    #pragma unroll
    for (int s = 0; s < 16; s++) z += g_pz[(size_t)s * BL + c];
    g_crcpz[c] = 1.f / z;
}

// vpT[b][d][l] *= rz[b][l], single fp16 plane
__global__ void __launch_bounds__(256) scale_vpT()
{
    size_t idx = (size_t)blockIdx.x * 256 + threadIdx.x;
    size_t e0  = idx * 8;
    int l   = (int)(e0 & (LL - 1));
    int row = (int)(e0 >> 11);
    int b   = row >> 9;
    uint4 hv = reinterpret_cast<uint4*>(g_vpTh)[idx];
    const float* rz = &g_crcpz[b * LL + l];
    uint32_t hw[4] = {hv.x, hv.y, hv.z, hv.w};
    #pragma unroll
    for (int p = 0; p < 4; p++) {
        __half2 hh;
        memcpy(&hh, &hw[p], 4);
        float v0 = __half2float(hh.x) * rz[2 * p];
        float v1 = __half2float(hh.y) * rz[2 * p + 1];
        hw[p] = packh2(v0, v1);
    }
    reinterpret_cast<uint4*>(g_vpTh)[idx] = make_uint4(hw[0], hw[1], hw[2], hw[3]);
}

// ---------------------------------------------------------------------------
extern "C" void kernel_launch(void* const* d_in, const int* in_sizes, int n_in,
                              void* d_out, int out_size)
{
    const float* q  = (const float*)d_in[0];
    const float* k  = (const float*)d_in[1];
    const float* v  = (const float*)d_in[2];
    const float* Wq = (const float*)d_in[3];
    const float* bq = (const float*)d_in[4];
    const float* Wk = (const float*)d_in[5];
    const float* bk = (const float*)d_in[6];
    const float* Wv = (const float*)d_in[7];
    const float* bv = (const float*)d_in[8];
    float* out = (float*)d_out;

    __half *qh, *ql, *kh, *kl, *vh;
    __half *Wqh, *Wql, *Wkh, *Wkl, *Wvh;
    __half *qph, *qpl, *kph, *vpTh, *Eh;
    cudaGetSymbolAddress((void**)&qh, g_qh);   cudaGetSymbolAddress((void**)&ql, g_ql);
    cudaGetSymbolAddress((void**)&kh, g_kh);   cudaGetSymbolAddress((void**)&kl, g_kl);
    cudaGetSymbolAddress((void**)&vh, g_vh);
    cudaGetSymbolAddress((void**)&Wqh, g_Wqh); cudaGetSymbolAddress((void**)&Wql, g_Wql);
    cudaGetSymbolAddress((void**)&Wkh, g_Wkh); cudaGetSymbolAddress((void**)&Wkl, g_Wkl);
    cudaGetSymbolAddress((void**)&Wvh, g_Wvh);
    cudaGetSymbolAddress((void**)&qph, g_qph); cudaGetSymbolAddress((void**)&qpl, g_qpl);
    cudaGetSymbolAddress((void**)&kph, g_kph);
    cudaGetSymbolAddress((void**)&vpTh, g_vpTh);
    cudaGetSymbolAddress((void**)&Eh, g_Eh);

    cudaFuncSetAttribute((const void*)gemm_mma<3, true>,
                         cudaFuncAttributeMaxDynamicSharedMemorySize, SMEM_BYTES);
    cudaFuncSetAttribute((const void*)gemm_mma<2, false>,
                         cudaFuncAttributeMaxDynamicSharedMemorySize, SMEM_BYTES);
    cudaFuncSetAttribute((const void*)gemm1_n64<0>,
                         cudaFuncAttributeMaxDynamicSharedMemorySize, SMEM1_BYTES);
    cudaFuncSetAttribute((const void*)gemm1_n64<2>,
                         cudaFuncAttributeMaxDynamicSharedMemorySize, SMEM1_BYTES);

    ProjArgs none = {};

    // 1) splits (v: hi plane only; Wv: hi plane only) — main stream (0)
    {
        dim3 gi((BL * DD) / 1024, 3);
        cvt3<<<gi, 256>>>(q, k, v, qh, ql, kh, kl, vh, nullptr);
        dim3 gw((DD * DD) / 1024, 3);
        cvt3<<<gw, 256>>>(Wq, Wk, Wv, Wqh, Wql, Wkh, Wkl, Wvh, nullptr);
    }

    // Fork: run v-proj on cudaStreamPerThread, concurrent with qk-proj/S-GEMM
    cudaEvent_t evFork, evJoin;
    cudaEventCreateWithFlags(&evFork, cudaEventDisableTiming);
    cudaEventCreateWithFlags(&evJoin, cudaEventDisableTiming);
    cudaEventRecord(evFork, 0);
    cudaStreamWaitEvent(cudaStreamPerThread, evFork, 0);

    // 2b) v projection on forked stream: 1-term, 128x64 tile, 3 CTAs/SM
    {
        dim3 gv(DD / 64, BL / 128, 1);
        gemm1_n64<2><<<gv, 256, SMEM1_BYTES, cudaStreamPerThread>>>(
            vh, Wvh, bv, nullptr, vpTh, DD, DD, 0, 0, 0);
    }
    cudaEventRecord(evJoin, cudaStreamPerThread);

    // 2a) q & k projections fused (z selects set); k writes SINGLE plane
    {
        ProjArgs pa;
        pa.Ah0 = qh; pa.Al0 = ql; pa.Bh0 = Wqh; pa.Bl0 = Wql;
        pa.b0 = bq; pa.Ch0 = qph; pa.Cl0 = qpl;
        pa.Ah1 = kh; pa.Al1 = kl; pa.Bh1 = Wkh; pa.Bl1 = Wkl;
        pa.b1 = bk; pa.Ch1 = kph; pa.Cl1 = nullptr;
        dim3 gqk(DD / 128, BL / 128, 2);
        gemm_mma<3, true><<<gqk, 256, SMEM_BYTES>>>(
            nullptr, nullptr, nullptr, nullptr, nullptr,
            nullptr, nullptr, DD, DD, 0, 0, 0, 1, pa);
    }

    // 3) E'[b] = exp(qp kp^T)*2^-26: 2-term, 128x128 tile, 4-stage + colsums
    {
        dim3 gs(LL / 128, LL / 128, BB);
        gemm_mma<2, false><<<gs, 256, SMEM_BYTES>>>(
            qph, qpl, kph, nullptr, nullptr,
            Eh, nullptr,
            LL, DD,
            (size_t)LL * DD, (size_t)LL * DD,
            (size_t)LL * LL, 3, none);
    }

    // 4) rz = 1/colsum(E'); join v-proj; fold rz into vpT
    colsum_combine<<<BL / 256, 256>>>();
    cudaStreamWaitEvent(0, evJoin, 0);
    scale_vpT<<<(BL * DD) / (8 * 256), 256>>>();

    cudaEventDestroy(evFork);
    cudaEventDestroy(evJoin);

    // 5) out[b] = E'[b] @ vpT'[b]^T  (1-term, 128x64 tile, 3 CTAs/SM)
    {
        dim3 go(DD / 64, LL / 128, BB);
        gemm1_n64<0><<<go, 256, SMEM1_BYTES>>>(
            Eh, vpTh, nullptr, out, nullptr,
            DD, LL,
            (size_t)LL * LL, (size_t)DD * LL,
            (size_t)LL * DD);
    }
}